// round 9
// baseline (speedup 1.0000x reference)
#include <cuda_runtime.h>

#define MAX_N 65536
#define NC 8                     // gather CTAs per graph

__device__ float g_p[MAX_N];     // x . w_rel  per node
__device__ float g_r[MAX_N];     // x . w_root per node
__device__ float g_svals[MAX_N]; // selected scores (per graph, k slots)
__device__ int   g_sidx[MAX_N];  // selected local indices
__device__ float g_part[1 << 19];// gather partials [B][NC][d]

// ---------------------------------------------------------------------------
// Kernel 1: per-node dual dot products (8 lanes/node, weights in smem).
// ---------------------------------------------------------------------------
__global__ void k_scores(const float4* __restrict__ x4,
                         const float4* __restrict__ wrel4,
                         const float4* __restrict__ wroot4,
                         int N, int d4) {
    extern __shared__ float4 wsm[];
    int t = threadIdx.x;
    for (int c = t; c < 2 * d4; c += blockDim.x)
        wsm[c] = (c < d4) ? wrel4[c] : wroot4[c - d4];
    __syncthreads();
    const float4* wa = wsm;
    const float4* wb = wsm + d4;

    int warp = (blockIdx.x * blockDim.x + t) >> 5;
    int lane = t & 31;
    int sub  = lane >> 3;
    int l8   = lane & 7;
    int node = warp * 4 + sub;
    if (node >= N) return;

    const float4* xr = x4 + (size_t)node * d4;
    float sp = 0.f, sr = 0.f;
#pragma unroll 8
    for (int c = l8; c < d4; c += 8) {
        float4 xv = xr[c];
        float4 a  = wa[c];
        float4 b  = wb[c];
        sp += xv.x * a.x + xv.y * a.y + xv.z * a.z + xv.w * a.w;
        sr += xv.x * b.x + xv.y * b.y + xv.z * b.z + xv.w * b.w;
    }
#pragma unroll
    for (int o = 4; o; o >>= 1) {
        sp += __shfl_xor_sync(0xffffffffu, sp, o);
        sr += __shfl_xor_sync(0xffffffffu, sr, o);
    }
    if (l8 == 0) {
        g_p[node] = sp;
        g_r[node] = sr;
    }
}

// ---------------------------------------------------------------------------
// Kernel 2: per-graph selection ONLY (grid B, 512 thr): smem edge aggregation,
// tanh scores, O(n) histogram exact top-k (jax tie-break) -> global lists.
// ---------------------------------------------------------------------------
__global__ __launch_bounds__(512)
void k_select(const int* __restrict__ ei,
              const float* __restrict__ brel,
              int n, int k, int E, int Eg) {
    extern __shared__ unsigned char sm[];
    float* p_s      = (float*)sm;                       // n
    float* agg_s    = p_s + n;                          // n
    unsigned* ubits = (unsigned*)(agg_s + n);           // n
    unsigned* hist  = ubits + n;                        // 256
    unsigned* cgt   = hist + 256;                       // 256
    uint2* list     = (uint2*)(cgt + 256);              // n
    int*   ctrl     = (int*)(list + n);                 // cnt, m, tb, krem

    const int g    = blockIdx.x;
    const int t    = threadIdx.x;
    const int base = g * n;
    const int nt   = blockDim.x;

    if (t < 4) ctrl[t] = 0;
    for (int b = t; b < 256; b += nt) hist[b] = 0;
    for (int i = t; i < n; i += nt) {
        p_s[i]   = g_p[base + i];
        agg_s[i] = 0.f;
    }
    __syncthreads();

    {   // edge aggregation, graph-local smem atomics
        const int eb = g * Eg;
        for (int e = t; e < Eg; e += nt) {
            int s  = ei[eb + e] - base;
            int dd = ei[E + eb + e] - base;
            atomicAdd(&agg_s[dd], p_s[s]);
        }
    }
    __syncthreads();

    // tanh score -> monotone bits + bucket histogram
    for (int i = t; i < n; i += nt) {
        float s = tanhf(agg_s[i] + brel[0] + g_r[base + i]);
        unsigned u = __float_as_uint(s);
        u = (u & 0x80000000u) ? ~u : (u | 0x80000000u);
        ubits[i] = u;
        atomicAdd(&hist[u >> 24], 1u);
    }
    __syncthreads();

    // suffix counts + threshold bucket
    for (int b = t; b < 256; b += nt) {
        unsigned s = 0;
        for (int j = b + 1; j < 256; j++) s += hist[j];
        cgt[b] = s;
        if (s < (unsigned)k && (unsigned)k <= s + hist[b]) {
            ctrl[2] = b;
            ctrl[3] = k - (int)s;
        }
    }
    __syncthreads();

    const int tb   = ctrl[2];
    const int krem = ctrl[3];

    // emit clear winners; threshold bucket to fine list
    for (int i = t; i < n; i += nt) {
        unsigned u = ubits[i];
        int b = (int)(u >> 24);
        if (b > tb) {
            int pos = atomicAdd(&ctrl[0], 1);
            unsigned fu = (u & 0x80000000u) ? (u & 0x7fffffffu) : ~u;
            g_svals[g * k + pos] = __uint_as_float(fu);
            g_sidx[g * k + pos]  = i;
        } else if (b == tb) {
            int pos = atomicAdd(&ctrl[1], 1);
            list[pos] = make_uint2(u, (unsigned)i);
        }
    }
    __syncthreads();

    // fine rank within threshold bucket (smaller index wins ties)
    {
        const int m = ctrl[1];
        for (int j = t; j < m; j += nt) {
            uint2 me = list[j];
            int r = 0;
            for (int l = 0; l < m; l++) {
                uint2 o = list[l];
                r += (o.x > me.x) || (o.x == me.x && o.y < me.y);
            }
            if (r < krem) {
                int pos = atomicAdd(&ctrl[0], 1);
                unsigned fu = (me.x & 0x80000000u) ? (me.x & 0x7fffffffu) : ~me.x;
                g_svals[g * k + pos] = __uint_as_float(fu);
                g_sidx[g * k + pos]  = (int)me.y;
            }
        }
    }
}

// ---------------------------------------------------------------------------
// Kernel 3: gather (grid B*NC, 256 thr). CTA (g,c) weighted-sums its slice of
// selected rows; writes partial pooled vector to g_part[g][c][:].
// ---------------------------------------------------------------------------
__global__ __launch_bounds__(256)
void k_gather(const float4* __restrict__ x4,
              int n, int k, int d4, int kpc) {
    extern __shared__ unsigned char sm[];
    float* sv    = (float*)sm;                 // kpc
    int*   si    = (int*)(sv + kpc);           // kpc
    float4* part = (float4*)(si + kpc);        // nrep * d4

    const int gc = blockIdx.x;
    const int g  = gc / NC;
    const int c  = gc % NC;
    const int t  = threadIdx.x;
    const int nt = blockDim.x;
    const int base = g * n;

    const int j0  = c * kpc;
    const int cnt = min(j0 + kpc, k) - j0;
    for (int j = t; j < cnt; j += nt) {
        sv[j] = g_svals[g * k + j0 + j];
        si[j] = g_sidx[g * k + j0 + j];
    }
    __syncthreads();

    const int col4 = t % d4;
    const int rep  = t / d4;
    const int nrep = nt / d4;
    const int per  = (cnt + nrep - 1) / nrep;
    const int s0   = rep * per;
    const int s1   = min(s0 + per, cnt);

    float4 a0 = {0,0,0,0}, a1 = {0,0,0,0}, a2 = {0,0,0,0}, a3 = {0,0,0,0};
    int j = s0;
    for (; j + 4 <= s1; j += 4) {
        float v0 = sv[j], v1 = sv[j+1], v2 = sv[j+2], v3 = sv[j+3];
        int   r0 = si[j], r1 = si[j+1], r2 = si[j+2], r3 = si[j+3];
        float4 q0 = x4[(size_t)(base + r0) * d4 + col4];
        float4 q1 = x4[(size_t)(base + r1) * d4 + col4];
        float4 q2 = x4[(size_t)(base + r2) * d4 + col4];
        float4 q3 = x4[(size_t)(base + r3) * d4 + col4];
        a0.x += v0*q0.x; a0.y += v0*q0.y; a0.z += v0*q0.z; a0.w += v0*q0.w;
        a1.x += v1*q1.x; a1.y += v1*q1.y; a1.z += v1*q1.z; a1.w += v1*q1.w;
        a2.x += v2*q2.x; a2.y += v2*q2.y; a2.z += v2*q2.z; a2.w += v2*q2.w;
        a3.x += v3*q3.x; a3.y += v3*q3.y; a3.z += v3*q3.z; a3.w += v3*q3.w;
    }
    for (; j < s1; j++) {
        float v = sv[j];
        float4 q = x4[(size_t)(base + si[j]) * d4 + col4];
        a0.x += v*q.x; a0.y += v*q.y; a0.z += v*q.z; a0.w += v*q.w;
    }
    float4 s;
    s.x = a0.x + a1.x + a2.x + a3.x;
    s.y = a0.y + a1.y + a2.y + a3.y;
    s.z = a0.z + a1.z + a2.z + a3.z;
    s.w = a0.w + a1.w + a2.w + a3.w;
    part[rep * d4 + col4] = s;
    __syncthreads();

    if (t < d4) {
        float4 acc = part[t];
        for (int rr = 1; rr < nrep; rr++) {
            float4 q = part[rr * d4 + t];
            acc.x += q.x; acc.y += q.y; acc.z += q.z; acc.w += q.w;
        }
        ((float4*)g_part)[(size_t)gc * d4 + t] = acc;
    }
}

// ---------------------------------------------------------------------------
// Kernel 4: reduce NC partials -> pooled (in smem), project through wproj,
// add bias, write out. Grid B/GB blocks, each handles GB graphs.
// ---------------------------------------------------------------------------
__global__ __launch_bounds__(256)
void k_proj(const float* __restrict__ wproj,
            const float* __restrict__ bproj,
            float* __restrict__ out,
            int k, int d, int odim, int GB) {
    extern __shared__ float pooled[];          // GB * d
    const int g0 = blockIdx.x * GB;
    const int t  = threadIdx.x;
    const int nt = blockDim.x;
    const float inv_k = 1.0f / (float)k;

    for (int idx = t; idx < GB * d; idx += nt) {
        int gl  = idx / d;
        int col = idx % d;
        float s = 0.f;
#pragma unroll
        for (int c = 0; c < NC; c++)
            s += g_part[((size_t)(g0 + gl) * NC + c) * d + col];
        pooled[idx] = s * inv_k;
    }
    __syncthreads();

    for (int o = t; o < odim; o += nt) {
        float acc0 = bproj[o], acc1 = 0.f, acc2 = 0.f, acc3 = 0.f;
        // GB accumulators per graph, chunked over d for MLP on wproj loads
        float accg[8];
#pragma unroll
        for (int gl = 0; gl < 8; gl++) accg[gl] = 0.f;
        for (int dd = 0; dd < d; dd += 4) {
            float w0 = wproj[(size_t)(dd + 0) * odim + o];
            float w1 = wproj[(size_t)(dd + 1) * odim + o];
            float w2 = wproj[(size_t)(dd + 2) * odim + o];
            float w3 = wproj[(size_t)(dd + 3) * odim + o];
            for (int gl = 0; gl < GB; gl++) {
                const float* pg = pooled + gl * d + dd;
                accg[gl] += pg[0] * w0 + pg[1] * w1 + pg[2] * w2 + pg[3] * w3;
            }
        }
        for (int gl = 0; gl < GB; gl++)
            out[(size_t)(g0 + gl) * odim + o] = bproj[o] + accg[gl];
        (void)acc0; (void)acc1; (void)acc2; (void)acc3;
    }
}

// ---------------------------------------------------------------------------
// Inputs: x, edge_index, batch, num_graphs, w_rel, b_rel, w_root, w_proj, b_proj.
// Output: [B, out_dim] float32.
// ---------------------------------------------------------------------------
extern "C" void kernel_launch(void* const* d_in, const int* in_sizes, int n_in,
                              void* d_out, int out_size) {
    const float* x     = (const float*)d_in[0];
    const int*   ei    = (const int*)d_in[1];
    const float* wrel  = (const float*)d_in[4];
    const float* brel  = (const float*)d_in[5];
    const float* wroot = (const float*)d_in[6];
    const float* wproj = (const float*)d_in[7];
    const float* bproj = (const float*)d_in[8];
    float* out = (float*)d_out;

    const int odim = in_sizes[8];
    const int d    = in_sizes[7] / odim;
    const int N    = in_sizes[0] / d;
    const int E    = in_sizes[1] / 2;
    const int B    = out_size / odim;
    const int n    = N / B;
    const int k    = (n + 1) / 2;       // ceil(0.5*n), RATIO = 0.5
    const int Eg   = E / B;
    const int d4   = d / 4;
    const int kpc  = (k + NC - 1) / NC; // selected nodes per gather CTA

    // K1: scores
    int warps = (N + 3) / 4;
    size_t smem1 = (size_t)(2 * d4) * sizeof(float4);
    k_scores<<<(warps * 32 + 255) / 256, 256, smem1>>>(
        (const float4*)x, (const float4*)wrel, (const float4*)wroot, N, d4);

    // K2: selection (per graph)
    size_t smem2 = (size_t)n * 8        // p, agg
                 + (size_t)n * 4        // ubits
                 + 512 * 4              // hist + cgt
                 + (size_t)n * 8        // list
                 + 32;                  // ctrl
    k_select<<<B, 512, smem2>>>(ei, brel, n, k, E, Eg);

    // K3: gather (NC CTAs per graph)
    const int nrep = 256 / d4;
    size_t smem3 = (size_t)kpc * 8 + (size_t)nrep * d4 * sizeof(float4);
    k_gather<<<B * NC, 256, smem3>>>((const float4*)x, n, k, d4, kpc);

    // K4: reduce + projection
    const int GB = 4;
    size_t smem4 = (size_t)GB * d * sizeof(float);
    k_proj<<<B / GB, 256, smem4>>>(wproj, bproj, out, k, d, odim, GB);
}

// round 10
// speedup vs baseline: 1.8896x; 1.8896x over previous
#include <cuda_runtime.h>

#define MAX_N 65536

__device__ float g_p[MAX_N];    // x . w_rel  per node
__device__ float g_r[MAX_N];    // x . w_root per node

// ---------------------------------------------------------------------------
// Kernel 1: per-node dual dot products. 8 lanes per node (4 nodes/warp),
// weights in shared memory.
// ---------------------------------------------------------------------------
__global__ void k_scores(const float4* __restrict__ x4,
                         const float4* __restrict__ wrel4,
                         const float4* __restrict__ wroot4,
                         int N, int d4) {
    extern __shared__ float4 wsm[];
    int t = threadIdx.x;
    for (int c = t; c < 2 * d4; c += blockDim.x)
        wsm[c] = (c < d4) ? wrel4[c] : wroot4[c - d4];
    __syncthreads();
    const float4* wa = wsm;
    const float4* wb = wsm + d4;

    int warp = (blockIdx.x * blockDim.x + t) >> 5;
    int lane = t & 31;
    int sub  = lane >> 3;
    int l8   = lane & 7;
    int node = warp * 4 + sub;
    if (node >= N) return;

    const float4* xr = x4 + (size_t)node * d4;
    float sp = 0.f, sr = 0.f;
#pragma unroll 8
    for (int c = l8; c < d4; c += 8) {
        float4 xv = xr[c];
        float4 a  = wa[c];
        float4 b  = wb[c];
        sp += xv.x * a.x + xv.y * a.y + xv.z * a.z + xv.w * a.w;
        sr += xv.x * b.x + xv.y * b.y + xv.z * b.z + xv.w * b.w;
    }
#pragma unroll
    for (int o = 4; o; o >>= 1) {
        sp += __shfl_xor_sync(0xffffffffu, sp, o);
        sr += __shfl_xor_sync(0xffffffffu, sr, o);
    }
    if (l8 == 0) {
        g_p[node] = sp;
        g_r[node] = sr;
    }
}

// ---------------------------------------------------------------------------
// Kernel 2 (per-graph, 1024 threads): smem edge aggregation, tanh scores,
// O(n) histogram top-k (exact, jax tie-break, shuffle-scan suffix counts),
// float4 gather, vectorized low-instruction projection.
// ---------------------------------------------------------------------------
__global__ __launch_bounds__(1024, 1)
void k_pool(const float* __restrict__ x,
            const int* __restrict__ ei,
            const float* __restrict__ brel,
            const float* __restrict__ wproj,
            const float* __restrict__ bproj,
            float* __restrict__ out,
            int n, int k, int d, int odim, int E, int Eg, int nrep4) {
    extern __shared__ unsigned char sm[];
    float* p_s     = (float*)sm;                                 // n
    float* agg_s   = p_s + n;                                    // n
    float* svals   = agg_s + n;                                  // k
    int*   sidx    = (int*)(svals + k);                          // k
    unsigned* hist = (unsigned*)(sidx + k);                      // 256
    unsigned* wtot = hist + 256;                                 // 8 warp totals
    uint2* list    = (uint2*)(wtot + 8);                         // n (u, idx)
    float* part    = (float*)(list + n);                         // nrep4 * d
    float* pooled  = part + nrep4 * d;                           // d
    int*   ctrl    = (int*)(pooled + d);                         // cnt, m, tb, krem

    const int g    = blockIdx.x;
    const int t    = threadIdx.x;
    const int base = g * n;
    const int nt   = blockDim.x;

    if (t < 4) ctrl[t] = 0;
    for (int b = t; b < 256; b += nt) hist[b] = 0;
    for (int i = t; i < n; i += nt) {
        p_s[i]   = g_p[base + i];
        agg_s[i] = 0.f;
    }
    __syncthreads();

    // ---- edge aggregation (graph-local, smem atomics) ----
    {
        const int eb = g * Eg;
        for (int e = t; e < Eg; e += nt) {
            int s  = ei[eb + e] - base;
            int dd = ei[E + eb + e] - base;
            atomicAdd(&agg_s[dd], p_s[s]);
        }
    }
    __syncthreads();

    // ---- tanh score -> monotone u32 bits (register) + bucket histogram ----
    unsigned myu = 0;
    if (t < n) {
        float s = tanhf(agg_s[t] + brel[0] + g_r[base + t]);
        unsigned u = __float_as_uint(s);
        myu = (u & 0x80000000u) ? ~u : (u | 0x80000000u);
        atomicAdd(&hist[myu >> 24], 1u);
    }
    __syncthreads();

    // ---- suffix counts via warp shuffle scan (no per-thread 255-loop) ----
    unsigned h_b = 0, s_in = 0;
    if (t < 256) {
        h_b  = hist[t];
        s_in = h_b;
        unsigned lane = t & 31;
#pragma unroll
        for (int off = 1; off < 32; off <<= 1) {
            unsigned v = __shfl_down_sync(0xffffffffu, s_in, off);
            if (lane + off < 32) s_in += v;
        }
        if (lane == 0) wtot[t >> 5] = s_in;   // warp-inclusive suffix from lane 0 = warp total
    }
    __syncthreads();
    if (t < 256) {
        unsigned w = t >> 5;
        unsigned ws = 0;
        for (unsigned j = w + 1; j < 8; j++) ws += wtot[j];
        unsigned incl = s_in + ws;            // # elements in buckets >= t (from this lane up)
        unsigned excl = incl - h_b;           // # elements in buckets > t
        if (excl < (unsigned)k && (unsigned)k <= incl) {
            ctrl[2] = t;                      // threshold bucket
            ctrl[3] = k - (int)excl;          // how many to take from it
        }
    }
    __syncthreads();

    const int tb   = ctrl[2];
    const int krem = ctrl[3];

    // ---- emit: clear winners outright; threshold bucket -> fine list ----
    if (t < n) {
        int b = (int)(myu >> 24);
        if (b > tb) {
            int pos = atomicAdd(&ctrl[0], 1);
            unsigned fu = (myu & 0x80000000u) ? (myu & 0x7fffffffu) : ~myu;
            svals[pos] = __uint_as_float(fu);
            sidx[pos]  = t;
        } else if (b == tb) {
            int pos = atomicAdd(&ctrl[1], 1);
            list[pos] = make_uint2(myu, (unsigned)t);
        }
    }
    __syncthreads();

    // ---- fine rank within threshold bucket (smaller index wins ties) ----
    {
        const int m = ctrl[1];
        if (t < m) {
            uint2 me = list[t];
            int r = 0;
            for (int l = 0; l < m; l++) {
                uint2 o = list[l];
                r += (o.x > me.x) || (o.x == me.x && o.y < me.y);
            }
            if (r < krem) {
                int pos = atomicAdd(&ctrl[0], 1);
                unsigned fu = (me.x & 0x80000000u) ? (me.x & 0x7fffffffu) : ~me.x;
                svals[pos] = __uint_as_float(fu);
                sidx[pos]  = (int)me.y;
            }
        }
    }
    __syncthreads();

    // ---- weighted mean: float4 gather, nrep4 replicas over nodes ----
    {
        const int d4   = d >> 2;
        const int col4 = t % d4;
        const int rep  = t / d4;
        const int per  = (k + nrep4 - 1) / nrep4;
        const int j0   = rep * per;
        const int j1   = min(j0 + per, k);
        const float4* x4 = (const float4*)x;
        float4 a0 = {0,0,0,0}, a1 = {0,0,0,0}, a2 = {0,0,0,0}, a3 = {0,0,0,0};
        int j = j0;
        for (; j + 4 <= j1; j += 4) {
            float v0 = svals[j], v1 = svals[j+1], v2 = svals[j+2], v3 = svals[j+3];
            int   r0 = sidx[j],  r1 = sidx[j+1],  r2 = sidx[j+2],  r3 = sidx[j+3];
            float4 q0 = x4[(size_t)(base + r0) * d4 + col4];
            float4 q1 = x4[(size_t)(base + r1) * d4 + col4];
            float4 q2 = x4[(size_t)(base + r2) * d4 + col4];
            float4 q3 = x4[(size_t)(base + r3) * d4 + col4];
            a0.x += v0*q0.x; a0.y += v0*q0.y; a0.z += v0*q0.z; a0.w += v0*q0.w;
            a1.x += v1*q1.x; a1.y += v1*q1.y; a1.z += v1*q1.z; a1.w += v1*q1.w;
            a2.x += v2*q2.x; a2.y += v2*q2.y; a2.z += v2*q2.z; a2.w += v2*q2.w;
            a3.x += v3*q3.x; a3.y += v3*q3.y; a3.z += v3*q3.z; a3.w += v3*q3.w;
        }
        for (; j < j1; j++) {
            float v = svals[j];
            float4 q = x4[(size_t)(base + sidx[j]) * d4 + col4];
            a0.x += v*q.x; a0.y += v*q.y; a0.z += v*q.z; a0.w += v*q.w;
        }
        float4 s;
        s.x = a0.x + a1.x + a2.x + a3.x;
        s.y = a0.y + a1.y + a2.y + a3.y;
        s.z = a0.z + a1.z + a2.z + a3.z;
        s.w = a0.w + a1.w + a2.w + a3.w;
        ((float4*)part)[rep * (d >> 2) + col4] = s;
    }
    __syncthreads();

    if (t < d) {
        float s = 0.f;
        for (int rr = 0; rr < nrep4; rr++) s += part[rr * d + t];
        pooled[t] = s / (float)k;
    }
    __syncthreads();

    // ---- projection (vectorized): thread -> 4 consecutive outputs, 16 d-reps
    {
        const int od4   = odim >> 2;           // float4 outputs (64)
        const int o4    = t % od4;
        const int rep   = t / od4;
        const int nrepP = nt / od4;            // 16
        const int chunk = d / nrepP;           // 16
        const int d0 = rep * chunk, d1 = d0 + chunk;
        const float4* w4 = (const float4*)wproj;
        float4 acc = {0, 0, 0, 0};
#pragma unroll 4
        for (int dd = d0; dd < d1; dd++) {
            float pv = pooled[dd];             // LDS broadcast within rep
            float4 w = w4[(size_t)dd * od4 + o4];
            acc.x += pv * w.x; acc.y += pv * w.y;
            acc.z += pv * w.z; acc.w += pv * w.w;
        }
        ((float4*)part)[rep * od4 + o4] = acc;
    }
    __syncthreads();

    {
        const int od4   = odim >> 2;
        const int nrepP = nt / od4;
        if (t < od4) {
            float4 acc = ((float4*)part)[t];
            for (int rr = 1; rr < nrepP; rr++) {
                float4 q = ((float4*)part)[rr * od4 + t];
                acc.x += q.x; acc.y += q.y; acc.z += q.z; acc.w += q.w;
            }
            float4 b = ((const float4*)bproj)[t];
            float4 o;
            o.x = acc.x + b.x; o.y = acc.y + b.y;
            o.z = acc.z + b.z; o.w = acc.w + b.w;
            ((float4*)out)[(size_t)g * od4 + t] = o;
        }
    }
}

// ---------------------------------------------------------------------------
// Inputs: x, edge_index, batch, num_graphs, w_rel, b_rel, w_root, w_proj, b_proj.
// Output: [B, out_dim] float32.
// ---------------------------------------------------------------------------
extern "C" void kernel_launch(void* const* d_in, const int* in_sizes, int n_in,
                              void* d_out, int out_size) {
    const float* x     = (const float*)d_in[0];
    const int*   ei    = (const int*)d_in[1];
    const float* wrel  = (const float*)d_in[4];
    const float* brel  = (const float*)d_in[5];
    const float* wroot = (const float*)d_in[6];
    const float* wproj = (const float*)d_in[7];
    const float* bproj = (const float*)d_in[8];
    float* out = (float*)d_out;

    const int odim = in_sizes[8];
    const int d    = in_sizes[7] / odim;
    const int N    = in_sizes[0] / d;
    const int E    = in_sizes[1] / 2;
    const int B    = out_size / odim;
    const int n    = N / B;
    const int k    = (n + 1) / 2;     // ceil(0.5 * n), RATIO = 0.5
    const int Eg   = E / B;
    const int d4   = d / 4;
    const int nrep4 = 1024 / d4;      // 16 for d=256

    // K1
    int warps = (N + 3) / 4;
    size_t smem1 = (size_t)(2 * d4) * sizeof(float4);
    k_scores<<<(warps * 32 + 255) / 256, 256, smem1>>>(
        (const float4*)x, (const float4*)wrel, (const float4*)wroot, N, d4);

    // K2
    const int pd = d > odim ? d : odim;
    size_t smem2 = (size_t)n * 8                 // p, agg
                 + (size_t)k * 8                 // svals + sidx
                 + 264 * 4                       // hist + wtot
                 + (size_t)n * 8                 // fine list
                 + (size_t)nrep4 * pd * 4        // part
                 + (size_t)d * 4                 // pooled
                 + 32;                           // ctrl + pad
    k_pool<<<B, 1024, smem2>>>(x, ei, brel, wproj, bproj, out,
                               n, k, d, odim, E, Eg, nrep4);
}